// round 1
// baseline (speedup 1.0000x reference)
#include <cuda_runtime.h>
#include <cstdint>

#define N_NODES 100000
#define N_EDGES 1600000
#define IN_F    512
#define OUT_F   256

// Scratch (no cudaMalloc allowed): H = tanh(XW), T = A*H. Final A*T -> d_out.
__device__ float g_H[(size_t)N_NODES * OUT_F];
__device__ float g_T[(size_t)N_NODES * OUT_F];
__device__ int   g_row_ptr[N_NODES + 1];

// ---------------------------------------------------------------------------
// GEMM + tanh: C[M,256] = tanh(A[M,512] @ B[512,256])
// 128x128x16 tile, 256 threads, 8x8 per-thread microtile.
// ---------------------------------------------------------------------------
__global__ __launch_bounds__(256, 2) void gemm_tanh_kernel(
    const float* __restrict__ A, const float* __restrict__ B, float* __restrict__ C)
{
    __shared__ float As[16][128];   // transposed: As[k][m]
    __shared__ float Bs[16][128];   // Bs[k][n]

    const int tid = threadIdx.x;
    const int m0  = blockIdx.y * 128;
    const int n0  = blockIdx.x * 128;
    const int tx  = tid & 15;       // 0..15 -> n
    const int ty  = tid >> 4;       // 0..15 -> m

    float acc[8][8];
    #pragma unroll
    for (int i = 0; i < 8; i++)
        #pragma unroll
        for (int j = 0; j < 8; j++) acc[i][j] = 0.0f;

    for (int k0 = 0; k0 < IN_F; k0 += 16) {
        // Load A tile: 128 rows x 16 k = 512 float4 (4 float4 per row along k)
        #pragma unroll
        for (int i = 0; i < 2; i++) {
            int f   = tid * 2 + i;      // 0..511
            int row = f >> 2;           // 0..127
            int kq  = f & 3;            // 0..3 (float4 index along k)
            float4 a4 = make_float4(0.f, 0.f, 0.f, 0.f);
            int grow = m0 + row;
            if (grow < N_NODES)
                a4 = *(const float4*)&A[(size_t)grow * IN_F + k0 + kq * 4];
            As[kq * 4 + 0][row] = a4.x;
            As[kq * 4 + 1][row] = a4.y;
            As[kq * 4 + 2][row] = a4.z;
            As[kq * 4 + 3][row] = a4.w;
        }
        // Load B tile: 16 k x 128 n = 512 float4
        #pragma unroll
        for (int i = 0; i < 2; i++) {
            int f  = tid * 2 + i;       // 0..511
            int kr = f >> 5;            // 0..15
            int nq = f & 31;            // 0..31
            float4 b4 = *(const float4*)&B[(size_t)(k0 + kr) * OUT_F + n0 + nq * 4];
            *(float4*)&Bs[kr][nq * 4] = b4;
        }
        __syncthreads();

        #pragma unroll
        for (int k = 0; k < 16; k++) {
            float a[8], b[8];
            *(float4*)&a[0] = *(const float4*)&As[k][ty * 8 + 0];
            *(float4*)&a[4] = *(const float4*)&As[k][ty * 8 + 4];
            *(float4*)&b[0] = *(const float4*)&Bs[k][tx * 8 + 0];
            *(float4*)&b[4] = *(const float4*)&Bs[k][tx * 8 + 4];
            #pragma unroll
            for (int i = 0; i < 8; i++)
                #pragma unroll
                for (int j = 0; j < 8; j++)
                    acc[i][j] = fmaf(a[i], b[j], acc[i][j]);
        }
        __syncthreads();
    }

    // Epilogue: tanh + store (accurate tanhf; cost negligible vs GEMM)
    #pragma unroll
    for (int i = 0; i < 8; i++) {
        int row = m0 + ty * 8 + i;
        if (row < N_NODES) {
            #pragma unroll
            for (int j = 0; j < 8; j += 4) {
                float4 v;
                v.x = tanhf(acc[i][j + 0]);
                v.y = tanhf(acc[i][j + 1]);
                v.z = tanhf(acc[i][j + 2]);
                v.w = tanhf(acc[i][j + 3]);
                *(float4*)&C[(size_t)row * OUT_F + n0 + tx * 8 + j] = v;
            }
        }
    }
}

// ---------------------------------------------------------------------------
// row_ptr[i] = lower_bound(row, i)  (row is sorted)
// ---------------------------------------------------------------------------
__global__ void row_ptr_kernel(const int* __restrict__ row)
{
    int i = blockIdx.x * blockDim.x + threadIdx.x;
    if (i > N_NODES) return;
    int lo = 0, hi = N_EDGES;
    while (lo < hi) {
        int mid = (lo + hi) >> 1;
        if (row[mid] < i) lo = mid + 1; else hi = mid;
    }
    g_row_ptr[i] = lo;
}

// ---------------------------------------------------------------------------
// SpMM: Y[r,:] = sum_e in seg(r) vals[e] * X[col[e],:]   (F=256)
// one warp per destination row; each lane owns 8 features (2 float4).
// X table (102.4 MB) fits in L2 -> gathers are L2 hits.
// ---------------------------------------------------------------------------
__global__ __launch_bounds__(256) void spmm_kernel(
    const int* __restrict__ col, const float* __restrict__ vals,
    const float* __restrict__ X, float* __restrict__ Y)
{
    int warp = (blockIdx.x * blockDim.x + threadIdx.x) >> 5;
    int lane = threadIdx.x & 31;
    if (warp >= N_NODES) return;

    int start = g_row_ptr[warp];
    int end   = g_row_ptr[warp + 1];

    float4 acc0 = make_float4(0.f, 0.f, 0.f, 0.f);
    float4 acc1 = make_float4(0.f, 0.f, 0.f, 0.f);

    for (int e = start; e < end; e++) {
        float v = __ldg(&vals[e]);
        int   c = __ldg(&col[e]);
        const float4* src = (const float4*)&X[(size_t)c * OUT_F + lane * 8];
        float4 x0 = __ldg(&src[0]);
        float4 x1 = __ldg(&src[1]);
        acc0.x = fmaf(v, x0.x, acc0.x);
        acc0.y = fmaf(v, x0.y, acc0.y);
        acc0.z = fmaf(v, x0.z, acc0.z);
        acc0.w = fmaf(v, x0.w, acc0.w);
        acc1.x = fmaf(v, x1.x, acc1.x);
        acc1.y = fmaf(v, x1.y, acc1.y);
        acc1.z = fmaf(v, x1.z, acc1.z);
        acc1.w = fmaf(v, x1.w, acc1.w);
    }

    float4* dst = (float4*)&Y[(size_t)warp * OUT_F + lane * 8];
    dst[0] = acc0;
    dst[1] = acc1;
}

// ---------------------------------------------------------------------------
extern "C" void kernel_launch(void* const* d_in, const int* in_sizes, int n_in,
                              void* d_out, int out_size)
{
    const float* features = (const float*)d_in[0];   // [100000, 512]
    const float* weight   = (const float*)d_in[1];   // [512, 256]
    const int*   row      = (const int*)d_in[2];     // [1.6M] sorted
    const int*   colv     = (const int*)d_in[3];     // [1.6M]
    const float* adj      = (const float*)d_in[4];   // [1.6M]
    float*       out      = (float*)d_out;           // [100000, 256]

    float* H = nullptr;
    float* T = nullptr;
    cudaGetSymbolAddress((void**)&H, g_H);
    cudaGetSymbolAddress((void**)&T, g_T);

    // 1. H = tanh(X @ W)
    dim3 ggrid(OUT_F / 128, (N_NODES + 127) / 128);
    gemm_tanh_kernel<<<ggrid, 256>>>(features, weight, H);

    // 2. row_ptr from sorted row
    row_ptr_kernel<<<(N_NODES + 1 + 255) / 256, 256>>>(row);

    // 3. T = A @ H
    int spmm_blocks = (N_NODES * 32 + 255) / 256;
    spmm_kernel<<<spmm_blocks, 256>>>(colv, adj, H, T);

    // 4. out = A @ T
    spmm_kernel<<<spmm_blocks, 256>>>(colv, adj, T, out);
}

// round 3
// speedup vs baseline: 1.2460x; 1.2460x over previous
#include <cuda_runtime.h>
#include <cuda_bf16.h>
#include <cstdint>

#define N_NODES 100000
#define N_EDGES 1600000
#define IN_F    512
#define OUT_F   256

// Scratch (no cudaMalloc): H = tanh(XW), T = A*H. Final A*T -> d_out.
__device__ float g_H[(size_t)N_NODES * OUT_F];
__device__ float g_T[(size_t)N_NODES * OUT_F];
__device__ int   g_row_ptr[N_NODES + 1];
// Pre-split weight (bf16 hi/lo), [512][256], L2-resident (512 KB total)
__device__ __nv_bfloat16 g_Bh[(size_t)IN_F * OUT_F];
__device__ __nv_bfloat16 g_Bl[(size_t)IN_F * OUT_F];

// ---------------------------------------------------------------------------
// helpers
// ---------------------------------------------------------------------------
__device__ __forceinline__ uint32_t smem_u32(const void* p) {
    uint32_t a;
    asm("{ .reg .u64 t; cvta.to.shared.u64 t, %1; cvt.u32.u64 %0, t; }" : "=r"(a) : "l"(p));
    return a;
}

__device__ __forceinline__ void ldsm_x4(uint32_t* r, uint32_t addr) {
    asm volatile("ldmatrix.sync.aligned.m8n8.x4.shared.b16 {%0,%1,%2,%3}, [%4];"
                 : "=r"(r[0]), "=r"(r[1]), "=r"(r[2]), "=r"(r[3]) : "r"(addr));
}
__device__ __forceinline__ void ldsm_x4_t(uint32_t* r, uint32_t addr) {
    asm volatile("ldmatrix.sync.aligned.m8n8.x4.trans.shared.b16 {%0,%1,%2,%3}, [%4];"
                 : "=r"(r[0]), "=r"(r[1]), "=r"(r[2]), "=r"(r[3]) : "r"(addr));
}
__device__ __forceinline__ void mma_bf16(float* c, const uint32_t* a, const uint32_t* b) {
    asm volatile(
        "mma.sync.aligned.m16n8k16.row.col.f32.bf16.bf16.f32 "
        "{%0,%1,%2,%3}, {%4,%5,%6,%7}, {%8,%9}, {%0,%1,%2,%3};"
        : "+f"(c[0]), "+f"(c[1]), "+f"(c[2]), "+f"(c[3])
        : "r"(a[0]), "r"(a[1]), "r"(a[2]), "r"(a[3]), "r"(b[0]), "r"(b[1]));
}

// ---------------------------------------------------------------------------
// Split W (fp32) -> bf16 hi/lo, once.
// ---------------------------------------------------------------------------
__global__ void bsplit_kernel(const float* __restrict__ W)
{
    int i = blockIdx.x * blockDim.x + threadIdx.x;
    if (i >= IN_F * OUT_F) return;
    float w = W[i];
    __nv_bfloat16 h = __float2bfloat16_rn(w);
    g_Bh[i] = h;
    g_Bl[i] = __float2bfloat16_rn(w - __bfloat162float(h));
}

// ---------------------------------------------------------------------------
// GEMM + tanh via mma.sync bf16 3-term split.
// Block tile 64x256 (BN = full OUT_F, A streamed once). 8 warps (2m x 4n),
// warp tile 32x64. BK=32, 16 chunks.
// smem: A hi/lo [64][40] bf16 (80B rows, ldmatrix conflict-free),
//       B hi/lo [32][264] bf16 (528B rows, conflict-free with .trans)
// ---------------------------------------------------------------------------
#define A_PAD 40
#define B_PAD 264
__global__ __launch_bounds__(256, 2) void gemm_tanh_mma_kernel(
    const float* __restrict__ A, float* __restrict__ C)
{
    __shared__ __nv_bfloat16 sAh[64 * A_PAD];
    __shared__ __nv_bfloat16 sAl[64 * A_PAD];
    __shared__ __nv_bfloat16 sBh[32 * B_PAD];
    __shared__ __nv_bfloat16 sBl[32 * B_PAD];

    const int tid  = threadIdx.x;
    const int wid  = tid >> 5, lane = tid & 31;
    const int mwarp = wid & 1, nwarp = wid >> 1;
    const int m0 = blockIdx.x * 64;

    const uint32_t sah = smem_u32(sAh), sal = smem_u32(sAl);
    const uint32_t sbh = smem_u32(sBh), sbl = smem_u32(sBl);

    // ldmatrix per-lane address bases
    const int q = lane >> 3, rr = lane & 7;
    uint32_t aOff[2];
    #pragma unroll
    for (int mt = 0; mt < 2; mt++) {
        int row  = mwarp * 32 + mt * 16 + (q & 1) * 8 + rr;
        int col8 = (q >> 1) * 8;
        aOff[mt] = (uint32_t)(row * A_PAD + col8) * 2;
    }
    const uint32_t bOff = (uint32_t)((((q & 1) * 8 + rr) * B_PAD) + nwarp * 64 + (q >> 1) * 8) * 2;

    // A load mapping: thread -> row tid/4, k-group (tid&3)*8
    const int ar  = tid >> 2;
    const int ak  = (tid & 3) * 8;
    // B copy mapping: thread -> k-row tid/8, n-off (tid&7)*32
    const int bkr = tid >> 3;
    const int bno = (tid & 7) * 32;

    float acc[2][8][4];
    #pragma unroll
    for (int i = 0; i < 2; i++)
        #pragma unroll
        for (int j = 0; j < 8; j++)
            #pragma unroll
            for (int l = 0; l < 4; l++) acc[i][j][l] = 0.0f;

    for (int ck = 0; ck < 16; ck++) {
        const int kc = ck * 32;

        // ---- A: 64 rows x 32 k fp32 -> hi/lo bf16 smem ----
        {
            int gr = m0 + ar;
            float f[8] = {0,0,0,0,0,0,0,0};
            if (gr < N_NODES) {
                const float4* p = (const float4*)&A[(size_t)gr * IN_F + kc + ak];
                float4 f0 = __ldg(&p[0]), f1 = __ldg(&p[1]);
                f[0]=f0.x; f[1]=f0.y; f[2]=f0.z; f[3]=f0.w;
                f[4]=f1.x; f[5]=f1.y; f[6]=f1.z; f[7]=f1.w;
            }
            uint32_t hw[4], lw[4];
            #pragma unroll
            for (int j = 0; j < 4; j++) {
                __nv_bfloat16 h0 = __float2bfloat16_rn(f[2*j]);
                __nv_bfloat16 h1 = __float2bfloat16_rn(f[2*j+1]);
                __nv_bfloat16 l0 = __float2bfloat16_rn(f[2*j]   - __bfloat162float(h0));
                __nv_bfloat16 l1 = __float2bfloat16_rn(f[2*j+1] - __bfloat162float(h1));
                hw[j] = ((uint32_t)__bfloat16_as_ushort(h1) << 16) | __bfloat16_as_ushort(h0);
                lw[j] = ((uint32_t)__bfloat16_as_ushort(l1) << 16) | __bfloat16_as_ushort(l0);
            }
            *(uint4*)&sAh[ar * A_PAD + ak] = make_uint4(hw[0], hw[1], hw[2], hw[3]);
            *(uint4*)&sAl[ar * A_PAD + ak] = make_uint4(lw[0], lw[1], lw[2], lw[3]);
        }
        // ---- B: copy pre-split bf16 chunk [32][256] ----
        {
            const size_t gb = (size_t)(kc + bkr) * OUT_F + bno;
            #pragma unroll
            for (int j = 0; j < 4; j++) {
                *(uint4*)&sBh[bkr * B_PAD + bno + j * 8] = __ldg((const uint4*)&g_Bh[gb + j * 8]);
                *(uint4*)&sBl[bkr * B_PAD + bno + j * 8] = __ldg((const uint4*)&g_Bl[gb + j * 8]);
            }
        }
        __syncthreads();

        // ---- MMA: 2 ksteps x (2 m-tiles x 8 n-tiles) x 3 terms ----
        #pragma unroll
        for (int s = 0; s < 2; s++) {
            uint32_t ah[2][4], al[2][4];
            ldsm_x4(ah[0], sah + aOff[0] + s * 32);
            ldsm_x4(ah[1], sah + aOff[1] + s * 32);
            ldsm_x4(al[0], sal + aOff[0] + s * 32);
            ldsm_x4(al[1], sal + aOff[1] + s * 32);
            #pragma unroll
            for (int np = 0; np < 4; np++) {
                uint32_t bh[4], bl[4];
                uint32_t baddr = bOff + (uint32_t)(s * 16 * B_PAD + np * 16) * 2;
                ldsm_x4_t(bh, sbh + baddr);
                ldsm_x4_t(bl, sbl + baddr);
                #pragma unroll
                for (int mt = 0; mt < 2; mt++) {
                    mma_bf16(acc[mt][2*np+0], ah[mt], bh + 0);
                    mma_bf16(acc[mt][2*np+1], ah[mt], bh + 2);
                    mma_bf16(acc[mt][2*np+0], al[mt], bh + 0);
                    mma_bf16(acc[mt][2*np+1], al[mt], bh + 2);
                    mma_bf16(acc[mt][2*np+0], ah[mt], bl + 0);
                    mma_bf16(acc[mt][2*np+1], ah[mt], bl + 2);
                }
            }
        }
        __syncthreads();
    }

    // ---- Epilogue: tanh + store ----
    const int gid = lane >> 2, tig = lane & 3;
    #pragma unroll
    for (int mt = 0; mt < 2; mt++) {
        int row = m0 + mwarp * 32 + mt * 16 + gid;
        #pragma unroll
        for (int nt = 0; nt < 8; nt++) {
            int col = nwarp * 64 + nt * 8 + tig * 2;
            if (row < N_NODES) {
                float2 v0 = make_float2(tanhf(acc[mt][nt][0]), tanhf(acc[mt][nt][1]));
                *(float2*)&C[(size_t)row * OUT_F + col] = v0;
            }
            if (row + 8 < N_NODES) {
                float2 v1 = make_float2(tanhf(acc[mt][nt][2]), tanhf(acc[mt][nt][3]));
                *(float2*)&C[(size_t)(row + 8) * OUT_F + col] = v1;
            }
        }
    }
}

// ---------------------------------------------------------------------------
// row_ptr[i] = lower_bound(row, i)  (row is sorted)
// ---------------------------------------------------------------------------
__global__ void row_ptr_kernel(const int* __restrict__ row)
{
    int i = blockIdx.x * blockDim.x + threadIdx.x;
    if (i > N_NODES) return;
    int lo = 0, hi = N_EDGES;
    while (lo < hi) {
        int mid = (lo + hi) >> 1;
        if (row[mid] < i) lo = mid + 1; else hi = mid;
    }
    g_row_ptr[i] = lo;
}

// ---------------------------------------------------------------------------
// SpMM: one warp per destination row; lane owns 8 features (2 float4).
// ---------------------------------------------------------------------------
__global__ __launch_bounds__(256) void spmm_kernel(
    const int* __restrict__ col, const float* __restrict__ vals,
    const float* __restrict__ X, float* __restrict__ Y)
{
    int warp = (blockIdx.x * blockDim.x + threadIdx.x) >> 5;
    int lane = threadIdx.x & 31;
    if (warp >= N_NODES) return;

    int start = g_row_ptr[warp];
    int end   = g_row_ptr[warp + 1];

    float4 acc0 = make_float4(0.f, 0.f, 0.f, 0.f);
    float4 acc1 = make_float4(0.f, 0.f, 0.f, 0.f);

    for (int e = start; e < end; e++) {
        float v = __ldcs(&vals[e]);
        int   c = __ldcs(&col[e]);
        const float4* src = (const float4*)&X[(size_t)c * OUT_F + lane * 8];
        float4 x0 = __ldg(&src[0]);
        float4 x1 = __ldg(&src[1]);
        acc0.x = fmaf(v, x0.x, acc0.x);
        acc0.y = fmaf(v, x0.y, acc0.y);
        acc0.z = fmaf(v, x0.z, acc0.z);
        acc0.w = fmaf(v, x0.w, acc0.w);
        acc1.x = fmaf(v, x1.x, acc1.x);
        acc1.y = fmaf(v, x1.y, acc1.y);
        acc1.z = fmaf(v, x1.z, acc1.z);
        acc1.w = fmaf(v, x1.w, acc1.w);
    }

    float4* dst = (float4*)&Y[(size_t)warp * OUT_F + lane * 8];
    __stcs(&dst[0], acc0);
    __stcs(&dst[1], acc1);
}

// ---------------------------------------------------------------------------
extern "C" void kernel_launch(void* const* d_in, const int* in_sizes, int n_in,
                              void* d_out, int out_size)
{
    const float* features = (const float*)d_in[0];
    const float* weight   = (const float*)d_in[1];
    const int*   row      = (const int*)d_in[2];
    const int*   colv     = (const int*)d_in[3];
    const float* adj      = (const float*)d_in[4];
    float*       out      = (float*)d_out;

    float* H = nullptr;
    float* T = nullptr;
    cudaGetSymbolAddress((void**)&H, g_H);
    cudaGetSymbolAddress((void**)&T, g_T);

    // 0. Split W into bf16 hi/lo (once per call; cheap)
    bsplit_kernel<<<(IN_F * OUT_F + 255) / 256, 256>>>(weight);

    // 1. H = tanh(X @ W) — mma.sync bf16 3-term split
    gemm_tanh_mma_kernel<<<(N_NODES + 63) / 64, 256>>>(features, H);

    // 2. row_ptr from sorted row
    row_ptr_kernel<<<(N_NODES + 1 + 255) / 256, 256>>>(row);

    // 3. T = A @ H
    int spmm_blocks = (N_NODES * 32 + 255) / 256;
    spmm_kernel<<<spmm_blocks, 256>>>(colv, adj, H, T);

    // 4. out = A @ T
    spmm_kernel<<<spmm_blocks, 256>>>(colv, adj, T, out);
}

// round 5
// speedup vs baseline: 2.6468x; 2.1242x over previous
#include <cuda_runtime.h>
#include <cuda_fp16.h>
#include <cstdint>

#define N_NODES 100000
#define N_EDGES 1600000
#define IN_F    512
#define OUT_F   256

// Scratch (no cudaMalloc). H and T are fp16 (range-safe: |H|<=1, |T|<~16).
__device__ __half g_H[(size_t)N_NODES * OUT_F];
__device__ __half g_T[(size_t)N_NODES * OUT_F];
__device__ int    g_row_ptr[N_NODES + 1];
// Pre-split weight (fp16 hi/lo), [512][256], 512 KB — L2-resident.
__device__ __half g_Wh[(size_t)IN_F * OUT_F];
__device__ __half g_Wl[(size_t)IN_F * OUT_F];

// ---------------------------------------------------------------------------
// helpers
// ---------------------------------------------------------------------------
__device__ __forceinline__ uint32_t smem_u32(const void* p) {
    uint32_t a;
    asm("{ .reg .u64 t; cvta.to.shared.u64 t, %1; cvt.u32.u64 %0, t; }" : "=r"(a) : "l"(p));
    return a;
}
__device__ __forceinline__ void ldsm_x4(uint32_t* r, uint32_t addr) {
    asm volatile("ldmatrix.sync.aligned.m8n8.x4.shared.b16 {%0,%1,%2,%3}, [%4];"
                 : "=r"(r[0]), "=r"(r[1]), "=r"(r[2]), "=r"(r[3]) : "r"(addr));
}
__device__ __forceinline__ void ldsm_x4_t(uint32_t* r, uint32_t addr) {
    asm volatile("ldmatrix.sync.aligned.m8n8.x4.trans.shared.b16 {%0,%1,%2,%3}, [%4];"
                 : "=r"(r[0]), "=r"(r[1]), "=r"(r[2]), "=r"(r[3]) : "r"(addr));
}
__device__ __forceinline__ void mma_f16(float* c, const uint32_t* a, const uint32_t* b) {
    asm volatile(
        "mma.sync.aligned.m16n8k16.row.col.f32.f16.f16.f32 "
        "{%0,%1,%2,%3}, {%4,%5,%6,%7}, {%8,%9}, {%0,%1,%2,%3};"
        : "+f"(c[0]), "+f"(c[1]), "+f"(c[2]), "+f"(c[3])
        : "r"(a[0]), "r"(a[1]), "r"(a[2]), "r"(a[3]), "r"(b[0]), "r"(b[1]));
}
__device__ __forceinline__ void cp16(uint32_t saddr, const void* gaddr) {
    asm volatile("cp.async.cg.shared.global [%0], [%1], 16;" :: "r"(saddr), "l"(gaddr));
}
#define CP_COMMIT() asm volatile("cp.async.commit_group;" ::: "memory")
#define CP_WAIT1()  asm volatile("cp.async.wait_group 1;" ::: "memory")

// ---------------------------------------------------------------------------
// Split W (fp32) -> fp16 hi/lo, once.
// ---------------------------------------------------------------------------
__global__ void wsplit_kernel(const float* __restrict__ W)
{
    int i = blockIdx.x * blockDim.x + threadIdx.x;
    if (i >= IN_F * OUT_F) return;
    float w = W[i];
    __half h = __float2half_rn(w);
    g_Wh[i] = h;
    g_Wl[i] = __float2half_rn(w - __half2float(h));
}

// ---------------------------------------------------------------------------
// GEMM + tanh: H[M,256] = tanh(A[M,512] @ W), fp16 2-term split (A*Wh + A*Wl).
// BM=128, BN=256 (full), BK=32 (16 chunks). 512 threads, 16 warps (4m x 4n),
// warp tile 32x64. cp.async double-buffered B, register-prefetched A.
// smem rows padded: A 40 halves (80B), B 264 halves (528B) — ldmatrix
// conflict-free.
// ---------------------------------------------------------------------------
#define A_PADH 40
#define B_PADH 264
#define SZ_A   (128 * A_PADH * 2)          // 10240 B per stage
#define SZ_B   (32 * B_PADH * 2)           // 16896 B per stage
#define OFF_A(st)   ((st) * SZ_A)
#define OFF_BH(st)  (2 * SZ_A + (st) * SZ_B)
#define OFF_BL(st)  (2 * SZ_A + 2 * SZ_B + (st) * SZ_B)
#define GEMM_SMEM   (2 * SZ_A + 4 * SZ_B)  // 88064 B

__global__ __launch_bounds__(512, 1) void gemm_tanh_kernel(
    const float* __restrict__ A, __half* __restrict__ H)
{
    extern __shared__ char smem[];
    const uint32_t sb = smem_u32(smem);
    const int tid  = threadIdx.x;
    const int wid  = tid >> 5, lane = tid & 31;
    const int mwarp = wid & 3, nwarp = wid >> 2;
    const int m0 = blockIdx.x * 128;

    // A load mapping: thread -> row tid/4 (0..127), k-off (tid&3)*8
    const int arow = tid >> 2;
    const int acol = (tid & 3) * 8;
    const bool avalid = (m0 + arow) < N_NODES;
    const float* abase = A + (size_t)(m0 + arow) * IN_F + acol;
    const uint32_t aSts = sb + (uint32_t)(arow * A_PADH + acol) * 2;  // within-stage

    // B copy mapping: thread -> k-row tid/16 (0..31), two 16B segs (tid&15)*2
    const int brow = tid >> 4;
    const int bseg = (tid & 15) * 2;
    const size_t  bsrc0 = (size_t)brow * OUT_F + bseg * 8;
    const uint32_t bSts = sb + (uint32_t)(brow * B_PADH + bseg * 8) * 2;

    // ldmatrix lane addressing (same pattern as validated round-3 kernel)
    const int q = lane >> 3, rr = lane & 7;
    uint32_t aOff[2];
    #pragma unroll
    for (int mt = 0; mt < 2; mt++) {
        int row  = mwarp * 32 + mt * 16 + (q & 1) * 8 + rr;
        int col8 = (q >> 1) * 8;
        aOff[mt] = (uint32_t)(row * A_PADH + col8) * 2;
    }
    const uint32_t bOff = (uint32_t)((((q & 1) * 8 + rr) * B_PADH) + nwarp * 64 + (q >> 1) * 8) * 2;

    float acc[2][8][4];
    #pragma unroll
    for (int i = 0; i < 2; i++)
        #pragma unroll
        for (int j = 0; j < 8; j++)
            #pragma unroll
            for (int l = 0; l < 4; l++) acc[i][j][l] = 0.0f;

    float4 pa[2][2];
    // prologue: A chunk 0 -> regs; B chunk 0 -> smem stage 0
    if (avalid) {
        pa[0][0] = __ldg((const float4*)(abase + 0));
        pa[0][1] = __ldg((const float4*)(abase + 4));
    } else {
        pa[0][0] = pa[0][1] = make_float4(0.f, 0.f, 0.f, 0.f);
    }
    {
        const __half* sh = g_Wh + bsrc0;
        const __half* sl = g_Wl + bsrc0;
        cp16(OFF_BH(0) + bSts,      sh);
        cp16(OFF_BH(0) + bSts + 16, sh + 8);
        cp16(OFF_BL(0) + bSts,      sl);
        cp16(OFF_BL(0) + bSts + 16, sl + 8);
    }
    CP_COMMIT();

    #pragma unroll
    for (int ck = 0; ck < 16; ck++) {
        const int st = ck & 1;
        // prefetch next B into other stage
        if (ck + 1 < 16) {
            const size_t o = (size_t)(ck + 1) * 32 * OUT_F + bsrc0;
            const __half* sh = g_Wh + o;
            const __half* sl = g_Wl + o;
            cp16(OFF_BH(st ^ 1) + bSts,      sh);
            cp16(OFF_BH(st ^ 1) + bSts + 16, sh + 8);
            cp16(OFF_BL(st ^ 1) + bSts,      sl);
            cp16(OFF_BL(st ^ 1) + bSts + 16, sl + 8);
        }
        CP_COMMIT();

        // convert + store A(ck) fp32 regs -> fp16 smem stage st
        {
            float f[8];
            f[0]=pa[st][0].x; f[1]=pa[st][0].y; f[2]=pa[st][0].z; f[3]=pa[st][0].w;
            f[4]=pa[st][1].x; f[5]=pa[st][1].y; f[6]=pa[st][1].z; f[7]=pa[st][1].w;
            __half2 h0 = __floats2half2_rn(f[0], f[1]);
            __half2 h1 = __floats2half2_rn(f[2], f[3]);
            __half2 h2 = __floats2half2_rn(f[4], f[5]);
            __half2 h3 = __floats2half2_rn(f[6], f[7]);
            uint4 u;
            u.x = *(uint32_t*)&h0; u.y = *(uint32_t*)&h1;
            u.z = *(uint32_t*)&h2; u.w = *(uint32_t*)&h3;
            *(uint4*)(smem + OFF_A(st) + (uint32_t)(arow * A_PADH + acol) * 2) = u;
        }
        // prefetch next A into regs (latency hidden by MMA below)
        if (ck + 1 < 16) {
            if (avalid) {
                pa[st ^ 1][0] = __ldg((const float4*)(abase + (ck + 1) * 32));
                pa[st ^ 1][1] = __ldg((const float4*)(abase + (ck + 1) * 32 + 4));
            }
        }
        CP_WAIT1();          // B(ck) arrived
        __syncthreads();

        // ---- MMA over stage st ----
        const uint32_t sa  = sb + OFF_A(st);
        const uint32_t sbh = sb + OFF_BH(st);
        const uint32_t sbl = sb + OFF_BL(st);
        #pragma unroll
        for (int s = 0; s < 2; s++) {
            uint32_t a[2][4];
            ldsm_x4(a[0], sa + aOff[0] + s * 32);
            ldsm_x4(a[1], sa + aOff[1] + s * 32);
            #pragma unroll
            for (int np = 0; np < 4; np++) {
                uint32_t bh[4], bl[4];
                uint32_t ba = bOff + (uint32_t)(s * 16 * B_PADH + np * 16) * 2;
                ldsm_x4_t(bh, sbh + ba);
                ldsm_x4_t(bl, sbl + ba);
                #pragma unroll
                for (int mt = 0; mt < 2; mt++) {
                    mma_f16(acc[mt][2*np+0], a[mt], bh + 0);
                    mma_f16(acc[mt][2*np+1], a[mt], bh + 2);
                    mma_f16(acc[mt][2*np+0], a[mt], bl + 0);
                    mma_f16(acc[mt][2*np+1], a[mt], bl + 2);
                }
            }
        }
        __syncthreads();
    }

    // ---- Epilogue: tanh + fp16 store ----
    const int gid = lane >> 2, tig = lane & 3;
    #pragma unroll
    for (int mt = 0; mt < 2; mt++) {
        int row = m0 + mwarp * 32 + mt * 16 + gid;
        #pragma unroll
        for (int nt = 0; nt < 8; nt++) {
            int col = nwarp * 64 + nt * 8 + tig * 2;
            if (row < N_NODES) {
                __half2 v = __floats2half2_rn(tanhf(acc[mt][nt][0]), tanhf(acc[mt][nt][1]));
                *(__half2*)&H[(size_t)row * OUT_F + col] = v;
            }
            if (row + 8 < N_NODES) {
                __half2 v = __floats2half2_rn(tanhf(acc[mt][nt][2]), tanhf(acc[mt][nt][3]));
                *(__half2*)&H[(size_t)(row + 8) * OUT_F + col] = v;
            }
        }
    }
}

// ---------------------------------------------------------------------------
// row_ptr[i] = lower_bound(row, i)  (row is sorted)
// ---------------------------------------------------------------------------
__global__ void row_ptr_kernel(const int* __restrict__ row)
{
    int i = blockIdx.x * blockDim.x + threadIdx.x;
    if (i > N_NODES) return;
    int lo = 0, hi = N_EDGES;
    while (lo < hi) {
        int mid = (lo + hi) >> 1;
        if (row[mid] < i) lo = mid + 1; else hi = mid;
    }
    g_row_ptr[i] = lo;
}

// ---------------------------------------------------------------------------
// SpMM with fp16 gather (512B/edge instead of 1KB — halves L2 traffic).
// one warp per destination row; lane owns 8 halves. fp32 accumulate.
// ---------------------------------------------------------------------------
__device__ __forceinline__ void spmm_accum(
    int start, int end, int lane,
    const int* __restrict__ col, const float* __restrict__ vals,
    const __half* __restrict__ X, float* acc)
{
    for (int e = start; e < end; e++) {
        float v = __ldcs(&vals[e]);
        int   c = __ldcs(&col[e]);
        uint4 x = __ldg((const uint4*)&X[(size_t)c * OUT_F + lane * 8]);
        const __half2* hx = (const __half2*)&x;
        #pragma unroll
        for (int j = 0; j < 4; j++) {
            float2 f = __half22float2(hx[j]);
            acc[2*j+0] = fmaf(v, f.x, acc[2*j+0]);
            acc[2*j+1] = fmaf(v, f.y, acc[2*j+1]);
        }
    }
}

__global__ __launch_bounds__(256) void spmm_h2h_kernel(
    const int* __restrict__ col, const float* __restrict__ vals,
    const __half* __restrict__ X, __half* __restrict__ Y)
{
    int warp = (blockIdx.x * blockDim.x + threadIdx.x) >> 5;
    int lane = threadIdx.x & 31;
    if (warp >= N_NODES) return;
    float acc[8] = {0,0,0,0,0,0,0,0};
    spmm_accum(g_row_ptr[warp], g_row_ptr[warp + 1], lane, col, vals, X, acc);
    __half2 h0 = __floats2half2_rn(acc[0], acc[1]);
    __half2 h1 = __floats2half2_rn(acc[2], acc[3]);
    __half2 h2 = __floats2half2_rn(acc[4], acc[5]);
    __half2 h3 = __floats2half2_rn(acc[6], acc[7]);
    uint4 u;
    u.x = *(uint32_t*)&h0; u.y = *(uint32_t*)&h1;
    u.z = *(uint32_t*)&h2; u.w = *(uint32_t*)&h3;
    __stcs((uint4*)&Y[(size_t)warp * OUT_F + lane * 8], u);
}

__global__ __launch_bounds__(256) void spmm_h2f_kernel(
    const int* __restrict__ col, const float* __restrict__ vals,
    const __half* __restrict__ X, float* __restrict__ Y)
{
    int warp = (blockIdx.x * blockDim.x + threadIdx.x) >> 5;
    int lane = threadIdx.x & 31;
    if (warp >= N_NODES) return;
    float acc[8] = {0,0,0,0,0,0,0,0};
    spmm_accum(g_row_ptr[warp], g_row_ptr[warp + 1], lane, col, vals, X, acc);
    float* dst = &Y[(size_t)warp * OUT_F + lane * 8];
    __stcs((float4*)&dst[0], make_float4(acc[0], acc[1], acc[2], acc[3]));
    __stcs((float4*)&dst[4], make_float4(acc[4], acc[5], acc[6], acc[7]));
}

// ---------------------------------------------------------------------------
extern "C" void kernel_launch(void* const* d_in, const int* in_sizes, int n_in,
                              void* d_out, int out_size)
{
    const float* features = (const float*)d_in[0];
    const float* weight   = (const float*)d_in[1];
    const int*   row      = (const int*)d_in[2];
    const int*   colv     = (const int*)d_in[3];
    const float* adj      = (const float*)d_in[4];
    float*       out      = (float*)d_out;

    __half* H = nullptr;
    __half* T = nullptr;
    cudaGetSymbolAddress((void**)&H, g_H);
    cudaGetSymbolAddress((void**)&T, g_T);

    cudaFuncSetAttribute(gemm_tanh_kernel,
                         cudaFuncAttributeMaxDynamicSharedMemorySize, GEMM_SMEM);

    // 0. Split W into fp16 hi/lo
    wsplit_kernel<<<(IN_F * OUT_F + 255) / 256, 256>>>(weight);

    // 1. H = tanh(X @ W), fp16 output
    gemm_tanh_kernel<<<(N_NODES + 127) / 128, 512, GEMM_SMEM>>>(features, H);

    // 2. row_ptr from sorted row
    row_ptr_kernel<<<(N_NODES + 1 + 255) / 256, 256>>>(row);

    // 3. T = A @ H   (fp16 -> fp16)
    int spmm_blocks = (N_NODES * 32 + 255) / 256;
    spmm_h2h_kernel<<<spmm_blocks, 256>>>(colv, adj, H, T);

    // 4. out = A @ T (fp16 -> fp32)
    spmm_h2f_kernel<<<spmm_blocks, 256>>>(colv, adj, T, out);
}

// round 7
// speedup vs baseline: 3.3034x; 1.2481x over previous
#include <cuda_runtime.h>
#include <cuda_fp16.h>
#include <cstdint>

#define N_NODES 100000
#define N_EDGES 1600000
#define IN_F    512
#define OUT_F   256

// Scratch (no cudaMalloc). H and T are fp16 (range-safe: |H|<=1, |T|<~16).
__device__ __half g_H[(size_t)N_NODES * OUT_F];
__device__ __half g_T[(size_t)N_NODES * OUT_F];
__device__ int    g_row_ptr[N_NODES + 1];
// fp16 weight [512][256], 256 KB — L2-resident.
__device__ __half g_Wh[(size_t)IN_F * OUT_F];

// ---------------------------------------------------------------------------
// helpers
// ---------------------------------------------------------------------------
__device__ __forceinline__ uint32_t smem_u32(const void* p) {
    uint32_t a;
    asm("{ .reg .u64 t; cvta.to.shared.u64 t, %1; cvt.u32.u64 %0, t; }" : "=r"(a) : "l"(p));
    return a;
}
__device__ __forceinline__ void ldsm_x4(uint32_t* r, uint32_t addr) {
    asm volatile("ldmatrix.sync.aligned.m8n8.x4.shared.b16 {%0,%1,%2,%3}, [%4];"
                 : "=r"(r[0]), "=r"(r[1]), "=r"(r[2]), "=r"(r[3]) : "r"(addr));
}
__device__ __forceinline__ void ldsm_x4_t(uint32_t* r, uint32_t addr) {
    asm volatile("ldmatrix.sync.aligned.m8n8.x4.trans.shared.b16 {%0,%1,%2,%3}, [%4];"
                 : "=r"(r[0]), "=r"(r[1]), "=r"(r[2]), "=r"(r[3]) : "r"(addr));
}
__device__ __forceinline__ void mma_f16(float* c, const uint32_t* a, const uint32_t* b) {
    asm volatile(
        "mma.sync.aligned.m16n8k16.row.col.f32.f16.f16.f32 "
        "{%0,%1,%2,%3}, {%4,%5,%6,%7}, {%8,%9}, {%0,%1,%2,%3};"
        : "+f"(c[0]), "+f"(c[1]), "+f"(c[2]), "+f"(c[3])
        : "r"(a[0]), "r"(a[1]), "r"(a[2]), "r"(a[3]), "r"(b[0]), "r"(b[1]));
}
__device__ __forceinline__ void cp16(uint32_t saddr, const void* gaddr) {
    asm volatile("cp.async.cg.shared.global [%0], [%1], 16;" :: "r"(saddr), "l"(gaddr));
}
#define CP_COMMIT() asm volatile("cp.async.commit_group;" ::: "memory")
#define CP_WAIT1()  asm volatile("cp.async.wait_group 1;" ::: "memory")

// ---------------------------------------------------------------------------
// Convert W (fp32) -> fp16, once.
// ---------------------------------------------------------------------------
__global__ void wconv_kernel(const float* __restrict__ W)
{
    int i = blockIdx.x * blockDim.x + threadIdx.x;
    if (i >= IN_F * OUT_F) return;
    g_Wh[i] = __float2half_rn(W[i]);
}

// ---------------------------------------------------------------------------
// GEMM + tanh: H[M,256] = tanh(A[M,512] @ W), 1-term fp16 (fp32 accum).
// BM=128, BN=256 (full), BK=32 (16 chunks). 512 threads, 16 warps (4m x 4n),
// warp tile 32x64. cp.async double-buffered B, register-prefetched A.
// ---------------------------------------------------------------------------
#define A_PADH 40
#define B_PADH 264
#define SZ_A   (128 * A_PADH * 2)          // 10240 B per stage
#define SZ_B   (32 * B_PADH * 2)           // 16896 B per stage
#define OFF_A(st)   ((st) * SZ_A)
#define OFF_BH(st)  (2 * SZ_A + (st) * SZ_B)
#define GEMM_SMEM   (2 * SZ_A + 2 * SZ_B)  // 54272 B

__global__ __launch_bounds__(512, 1) void gemm_tanh_kernel(
    const float* __restrict__ A, __half* __restrict__ H)
{
    extern __shared__ char smem[];
    const uint32_t sb = smem_u32(smem);
    const int tid  = threadIdx.x;
    const int wid  = tid >> 5, lane = tid & 31;
    const int mwarp = wid & 3, nwarp = wid >> 2;
    const int m0 = blockIdx.x * 128;

    // A load mapping: thread -> row tid/4 (0..127), k-off (tid&3)*8
    const int arow = tid >> 2;
    const int acol = (tid & 3) * 8;
    const bool avalid = (m0 + arow) < N_NODES;
    const float* abase = A + (size_t)(m0 + arow) * IN_F + acol;

    // B copy mapping: thread -> k-row tid/16 (0..31), two 16B segs (tid&15)*2
    const int brow = tid >> 4;
    const int bseg = (tid & 15) * 2;
    const size_t  bsrc0 = (size_t)brow * OUT_F + bseg * 8;
    const uint32_t bSts = sb + (uint32_t)(brow * B_PADH + bseg * 8) * 2;

    // ldmatrix lane addressing
    const int q = lane >> 3, rr = lane & 7;
    uint32_t aOff[2];
    #pragma unroll
    for (int mt = 0; mt < 2; mt++) {
        int row  = mwarp * 32 + mt * 16 + (q & 1) * 8 + rr;
        int col8 = (q >> 1) * 8;
        aOff[mt] = (uint32_t)(row * A_PADH + col8) * 2;
    }
    const uint32_t bOff = (uint32_t)((((q & 1) * 8 + rr) * B_PADH) + nwarp * 64 + (q >> 1) * 8) * 2;

    float acc[2][8][4];
    #pragma unroll
    for (int i = 0; i < 2; i++)
        #pragma unroll
        for (int j = 0; j < 8; j++)
            #pragma unroll
            for (int l = 0; l < 4; l++) acc[i][j][l] = 0.0f;

    float4 pa[2][2];
    // prologue: A chunk 0 -> regs; B chunk 0 -> smem stage 0
    if (avalid) {
        pa[0][0] = __ldg((const float4*)(abase + 0));
        pa[0][1] = __ldg((const float4*)(abase + 4));
    } else {
        pa[0][0] = pa[0][1] = make_float4(0.f, 0.f, 0.f, 0.f);
    }
    {
        const __half* sh = g_Wh + bsrc0;
        cp16(OFF_BH(0) + bSts,      sh);
        cp16(OFF_BH(0) + bSts + 16, sh + 8);
    }
    CP_COMMIT();

    #pragma unroll
    for (int ck = 0; ck < 16; ck++) {
        const int st = ck & 1;
        // prefetch next B into other stage
        if (ck + 1 < 16) {
            const size_t o = (size_t)(ck + 1) * 32 * OUT_F + bsrc0;
            const __half* sh = g_Wh + o;
            cp16(OFF_BH(st ^ 1) + bSts,      sh);
            cp16(OFF_BH(st ^ 1) + bSts + 16, sh + 8);
        }
        CP_COMMIT();

        // convert + store A(ck) fp32 regs -> fp16 smem stage st
        {
            __half2 h0 = __floats2half2_rn(pa[st][0].x, pa[st][0].y);
            __half2 h1 = __floats2half2_rn(pa[st][0].z, pa[st][0].w);
            __half2 h2 = __floats2half2_rn(pa[st][1].x, pa[st][1].y);
            __half2 h3 = __floats2half2_rn(pa[st][1].z, pa[st][1].w);
            uint4 u;
            u.x = *(uint32_t*)&h0; u.y = *(uint32_t*)&h1;
            u.z = *(uint32_t*)&h2; u.w = *(uint32_t*)&h3;
            *(uint4*)(smem + OFF_A(st) + (uint32_t)(arow * A_PADH + acol) * 2) = u;
        }
        // prefetch next A into regs (latency hidden by MMA below)
        if (ck + 1 < 16) {
            if (avalid) {
                pa[st ^ 1][0] = __ldg((const float4*)(abase + (ck + 1) * 32));
                pa[st ^ 1][1] = __ldg((const float4*)(abase + (ck + 1) * 32 + 4));
            }
        }
        CP_WAIT1();          // B(ck) arrived
        __syncthreads();

        // ---- MMA over stage st ----
        const uint32_t sa  = sb + OFF_A(st);
        const uint32_t sbh = sb + OFF_BH(st);
        #pragma unroll
        for (int s = 0; s < 2; s++) {
            uint32_t a[2][4];
            ldsm_x4(a[0], sa + aOff[0] + s * 32);
            ldsm_x4(a[1], sa + aOff[1] + s * 32);
            #pragma unroll
            for (int np = 0; np < 4; np++) {
                uint32_t bh[4];
                uint32_t ba = bOff + (uint32_t)(s * 16 * B_PADH + np * 16) * 2;
                ldsm_x4_t(bh, sbh + ba);
                #pragma unroll
                for (int mt = 0; mt < 2; mt++) {
                    mma_f16(acc[mt][2*np+0], a[mt], bh + 0);
                    mma_f16(acc[mt][2*np+1], a[mt], bh + 2);
                }
            }
        }
        __syncthreads();
    }

    // ---- Epilogue: tanh + fp16 store ----
    const int gid = lane >> 2, tig = lane & 3;
    #pragma unroll
    for (int mt = 0; mt < 2; mt++) {
        int row = m0 + mwarp * 32 + mt * 16 + gid;
        #pragma unroll
        for (int nt = 0; nt < 8; nt++) {
            int col = nwarp * 64 + nt * 8 + tig * 2;
            if (row < N_NODES) {
                __half2 v = __floats2half2_rn(tanhf(acc[mt][nt][0]), tanhf(acc[mt][nt][1]));
                *(__half2*)&H[(size_t)row * OUT_F + col] = v;
            }
            if (row + 8 < N_NODES) {
                __half2 v = __floats2half2_rn(tanhf(acc[mt][nt][2]), tanhf(acc[mt][nt][3]));
                *(__half2*)&H[(size_t)(row + 8) * OUT_F + col] = v;
            }
        }
    }
}

// ---------------------------------------------------------------------------
// row_ptr[i] = lower_bound(row, i)  (row is sorted)
// ---------------------------------------------------------------------------
__global__ void row_ptr_kernel(const int* __restrict__ row)
{
    int i = blockIdx.x * blockDim.x + threadIdx.x;
    if (i > N_NODES) return;
    int lo = 0, hi = N_EDGES;
    while (lo < hi) {
        int mid = (lo + hi) >> 1;
        if (row[mid] < i) lo = mid + 1; else hi = mid;
    }
    g_row_ptr[i] = lo;
}

// ---------------------------------------------------------------------------
// SpMM with fp16 gather; one warp per destination row; fp32 accumulate.
// ---------------------------------------------------------------------------
__device__ __forceinline__ void spmm_accum(
    int start, int end, int lane,
    const int* __restrict__ col, const float* __restrict__ vals,
    const __half* __restrict__ X, float* acc)
{
    for (int e = start; e < end; e++) {
        float v = __ldcs(&vals[e]);
        int   c = __ldcs(&col[e]);
        uint4 x = __ldg((const uint4*)&X[(size_t)c * OUT_F + lane * 8]);
        const __half2* hx = (const __half2*)&x;
        #pragma unroll
        for (int j = 0; j < 4; j++) {
            float2 f = __half22float2(hx[j]);
            acc[2*j+0] = fmaf(v, f.x, acc[2*j+0]);
            acc[2*j+1] = fmaf(v, f.y, acc[2*j+1]);
        }
    }
}

__global__ __launch_bounds__(256) void spmm_h2h_kernel(
    const int* __restrict__ col, const float* __restrict__ vals,
    const __half* __restrict__ X, __half* __restrict__ Y)
{
    int warp = (blockIdx.x * blockDim.x + threadIdx.x) >> 5;
    int lane = threadIdx.x & 31;
    if (warp >= N_NODES) return;
    float acc[8] = {0,0,0,0,0,0,0,0};
    spmm_accum(g_row_ptr[warp], g_row_ptr[warp + 1], lane, col, vals, X, acc);
    __half2 h0 = __floats2half2_rn(acc[0], acc[1]);
    __half2 h1 = __floats2half2_rn(acc[2], acc[3]);
    __half2 h2 = __floats2half2_rn(acc[4], acc[5]);
    __half2 h3 = __floats2half2_rn(acc[6], acc[7]);
    uint4 u;
    u.x = *(uint32_t*)&h0; u.y = *(uint32_t*)&h1;
    u.z = *(uint32_t*)&h2; u.w = *(uint32_t*)&h3;
    __stcs((uint4*)&Y[(size_t)warp * OUT_F + lane * 8], u);
}

__global__ __launch_bounds__(256) void spmm_h2f_kernel(
    const int* __restrict__ col, const float* __restrict__ vals,
    const __half* __restrict__ X, float* __restrict__ Y)
{
    int warp = (blockIdx.x * blockDim.x + threadIdx.x) >> 5;
    int lane = threadIdx.x & 31;
    if (warp >= N_NODES) return;
    float acc[8] = {0,0,0,0,0,0,0,0};
    spmm_accum(g_row_ptr[warp], g_row_ptr[warp + 1], lane, col, vals, X, acc);
    float* dst = &Y[(size_t)warp * OUT_F + lane * 8];
    __stcs((float4*)&dst[0], make_float4(acc[0], acc[1], acc[2], acc[3]));
    __stcs((float4*)&dst[4], make_float4(acc[4], acc[5], acc[6], acc[7]));
}

// ---------------------------------------------------------------------------
extern "C" void kernel_launch(void* const* d_in, const int* in_sizes, int n_in,
                              void* d_out, int out_size)
{
    const float* features = (const float*)d_in[0];
    const float* weight   = (const float*)d_in[1];
    const int*   row      = (const int*)d_in[2];
    const int*   colv     = (const int*)d_in[3];
    const float* adj      = (const float*)d_in[4];
    float*       out      = (float*)d_out;

    __half* H = nullptr;
    __half* T = nullptr;
    cudaGetSymbolAddress((void**)&H, g_H);
    cudaGetSymbolAddress((void**)&T, g_T);

    cudaFuncSetAttribute(gemm_tanh_kernel,
                         cudaFuncAttributeMaxDynamicSharedMemorySize, GEMM_SMEM);

    // 0. Convert W to fp16
    wconv_kernel<<<(IN_F * OUT_F + 255) / 256, 256>>>(weight);

    // 1. H = tanh(X @ W), fp16 output
    gemm_tanh_kernel<<<(N_NODES + 127) / 128, 512, GEMM_SMEM>>>(features, H);

    // 2. row_ptr from sorted row
    row_ptr_kernel<<<(N_NODES + 1 + 255) / 256, 256>>>(row);

    // 3. T = A @ H   (fp16 -> fp16)
    int spmm_blocks = (N_NODES * 32 + 255) / 256;
    spmm_h2h_kernel<<<spmm_blocks, 256>>>(colv, adj, H, T);

    // 4. out = A @ T (fp16 -> fp32)
    spmm_h2f_kernel<<<spmm_blocks, 256>>>(colv, adj, T, out);
}